// round 3
// baseline (speedup 1.0000x reference)
#include <cuda_runtime.h>
#include <cstdint>
#include <cstdio>

// Dual LSTM: B=512, T=128, I=128, H=512.
// One persistent kernel, 128 CTAs (all co-resident on 148 SMs), custom grid
// barrier once per timestep. TF32 mma.sync GEMM, c-state in registers,
// h ping-pong through device-global buffers with .cg (L2-coherent) access.

#define B_   512
#define T_   128
#define I_   128
#define H_   512
#define K_   640     // I + H
#define G4_  2048    // 4*H

#define MT   128     // batch rows per CTA
#define NT   32      // hidden cols per CTA (x4 gates = 128 gate cols)
#define NBLK 128
#define NTHREADS 256

#define SMEM_BYTES 66560

// persistent state
__device__ float    g_h[2][2][B_ * H_];   // [cell][parity][B*H]
__device__ unsigned g_arrive = 0;
__device__ unsigned g_release = 0;

__device__ __forceinline__ unsigned f2tf32(float x) {
    unsigned u;
    asm("cvt.rna.tf32.f32 %0, %1;" : "=r"(u) : "f"(x));
    return u;
}

__device__ __forceinline__ void mma8(float* d, const unsigned* a, const unsigned* b) {
    asm volatile(
        "mma.sync.aligned.m16n8k8.row.col.f32.tf32.tf32.f32 "
        "{%0,%1,%2,%3}, {%4,%5,%6,%7}, {%8,%9}, {%0,%1,%2,%3};\n"
        : "+f"(d[0]), "+f"(d[1]), "+f"(d[2]), "+f"(d[3])
        : "r"(a[0]), "r"(a[1]), "r"(a[2]), "r"(a[3]), "r"(b[0]), "r"(b[1]));
}

__device__ __forceinline__ void grid_sync() {
    __syncthreads();
    if (threadIdx.x == 0) {
        __threadfence();
        unsigned ticket = atomicAdd(&g_arrive, 1u) + 1u;
        unsigned target = (ticket + NBLK - 1u) / NBLK;   // generation to wait for
        if (ticket == target * NBLK) {
            atomicAdd(&g_release, 1u);                   // last arriver releases
        }
        unsigned r;
        for (;;) {
            asm volatile("ld.acquire.gpu.u32 %0, [%1];" : "=r"(r) : "l"(&g_release) : "memory");
            if (r >= target) break;
            __nanosleep(64);
        }
    }
    __syncthreads();
}

__device__ __forceinline__ float sigm(float x) { return 1.0f / (1.0f + expf(-x)); }

extern "C" __global__ void __launch_bounds__(NTHREADS, 1)
dual_lstm_kernel(const float* __restrict__ s_x, const float* __restrict__ l_x,
                 const float* __restrict__ s_W, const float* __restrict__ s_b,
                 const float* __restrict__ l_W, const float* __restrict__ l_b,
                 const float* __restrict__ oW,  const float* __restrict__ ob,
                 float* __restrict__ out)
{
    extern __shared__ unsigned char smem_raw[];
    unsigned* As = (unsigned*)smem_raw;     // [128][36] tf32
    unsigned* Bs = As + 128 * 36;           // [32][132] tf32
    float*    Gs = (float*)smem_raw;        // [128][128] gate exchange (reuses As/Bs)

    const int tid  = threadIdx.x;
    const int bid  = blockIdx.x;
    const int cell = bid >> 6;              // 0 = short, 1 = long
    const int rr   = bid & 63;
    const int mt   = rr >> 4;               // 0..3
    const int nt   = rr & 15;               // 0..15
    const int b0   = mt * MT;
    const int n0   = nt * NT;

    const float* x  = cell ? l_x : s_x;
    const float* W  = cell ? l_W : s_W;
    const float* bb = cell ? l_b : s_b;

    const int warp = tid >> 5, lane = tid & 31;
    const int wm = warp >> 2, wn = warp & 3;    // warp tile: 64 rows x 32 cols

    // ---- zero initial h (parity 0) for this CTA's owned patch ----
    {
        const int col = tid & 31, rg = tid >> 5;
        #pragma unroll
        for (int i = 0; i < 16; ++i) {
            int row = rg + (i << 3);
            __stcg(&g_h[cell][0][(size_t)(b0 + row) * H_ + n0 + col], 0.0f);
        }
    }

    // c-state in registers: thread owns (rows rg+8i, col), i<16
    float c_st[16];
    #pragma unroll
    for (int i = 0; i < 16; ++i) c_st[i] = 0.0f;

    float bias4[4];
    {
        const int col = tid & 31;
        #pragma unroll
        for (int g = 0; g < 4; ++g) bias4[g] = bb[g * H_ + n0 + col];
    }

    grid_sync();   // h zeros visible everywhere

    // ================== time loop ==================
    for (int t = 0; t < T_; ++t) {
        const float* hread  = g_h[cell][t & 1];
        float*       hwrite = g_h[cell][(t + 1) & 1];

        float acc[4][4][4];
        #pragma unroll
        for (int a = 0; a < 4; ++a)
            #pragma unroll
            for (int n = 0; n < 4; ++n)
                #pragma unroll
                for (int r = 0; r < 4; ++r) acc[a][n][r] = 0.0f;

        for (int kt = 0; kt < 20; ++kt) {
            const int k0 = kt * 32;
            // ---- fill A tile [128 rows][32 k] (x for kt<4, h for kt>=4) ----
            #pragma unroll
            for (int i = 0; i < 4; ++i) {
                int e  = tid + i * 256;      // float4 index, 1024 total
                int m  = e >> 3;
                int kk = (e & 7) << 2;
                float4 v;
                if (k0 < I_) {
                    v = __ldg((const float4*)(x + (size_t)(b0 + m) * (T_ * I_) +
                                              (size_t)t * I_ + k0 + kk));
                } else {
                    v = __ldcg((const float4*)(hread + (size_t)(b0 + m) * H_ +
                                               (k0 - I_) + kk));
                }
                unsigned* d = As + m * 36 + kk;
                d[0] = f2tf32(v.x); d[1] = f2tf32(v.y);
                d[2] = f2tf32(v.z); d[3] = f2tf32(v.w);
            }
            // ---- fill B tile [32 k][128 gate-cols: 4 gates x 32] ----
            #pragma unroll
            for (int i = 0; i < 4; ++i) {
                int e   = tid + i * 256;     // float4 index, 1024 total
                int kk  = e >> 5;
                int c   = (e & 31) << 2;
                int gat = c >> 5;
                int cin = c & 31;
                float4 v = __ldg((const float4*)(W + (size_t)(k0 + kk) * G4_ +
                                                 gat * H_ + n0 + cin));
                unsigned* d = Bs + kk * 132 + c;
                d[0] = f2tf32(v.x); d[1] = f2tf32(v.y);
                d[2] = f2tf32(v.z); d[3] = f2tf32(v.w);
            }
            __syncthreads();
            // ---- compute: 4 k-chunks of 8, 16 mma each ----
            #pragma unroll
            for (int kc = 0; kc < 32; kc += 8) {
                unsigned af[4][4];
                #pragma unroll
                for (int mf = 0; mf < 4; ++mf) {
                    int rb = wm * 64 + mf * 16;
                    const unsigned* p = As + (rb + (lane >> 2)) * 36 + kc + (lane & 3);
                    af[mf][0] = p[0];
                    af[mf][1] = p[8 * 36];
                    af[mf][2] = p[4];
                    af[mf][3] = p[8 * 36 + 4];
                }
                unsigned bf[4][2];
                #pragma unroll
                for (int nf = 0; nf < 4; ++nf) {
                    int cb = wn * 32 + nf * 8;
                    const unsigned* p = Bs + (kc + (lane & 3)) * 132 + cb + (lane >> 2);
                    bf[nf][0] = p[0];
                    bf[nf][1] = p[4 * 132];
                }
                #pragma unroll
                for (int mf = 0; mf < 4; ++mf)
                    #pragma unroll
                    for (int nf = 0; nf < 4; ++nf)
                        mma8(acc[mf][nf], af[mf], bf[nf]);
            }
            __syncthreads();
        }

        // ---- dump G to smem for gate-math exchange ----
        #pragma unroll
        for (int mf = 0; mf < 4; ++mf) {
            int r0 = wm * 64 + mf * 16 + (lane >> 2);
            #pragma unroll
            for (int nf = 0; nf < 4; ++nf) {
                int cb = wn * 32 + nf * 8 + ((lane & 3) << 1);
                Gs[r0 * 128 + cb]             = acc[mf][nf][0];
                Gs[r0 * 128 + cb + 1]         = acc[mf][nf][1];
                Gs[(r0 + 8) * 128 + cb]       = acc[mf][nf][2];
                Gs[(r0 + 8) * 128 + cb + 1]   = acc[mf][nf][3];
            }
        }
        __syncthreads();

        // ---- gate math (c in registers, h to global .cg) ----
        {
            const int col = tid & 31, rg = tid >> 5;
            #pragma unroll
            for (int i = 0; i < 16; ++i) {
                int row  = rg + (i << 3);
                float f  = Gs[row * 128 +  0 + col] + bias4[0];
                float ii = Gs[row * 128 + 32 + col] + bias4[1];
                float o  = Gs[row * 128 + 64 + col] + bias4[2];
                float cd = Gs[row * 128 + 96 + col] + bias4[3];
                float c  = sigm(f) * c_st[i] + sigm(ii) * tanhf(cd);
                c_st[i]  = c;
                __stcg(&hwrite[(size_t)(b0 + row) * H_ + n0 + col],
                       sigm(o) * tanhf(c));
            }
        }
        grid_sync();
    }

    // ================== epilogue: out = tanh([sh,lh] @ oW + ob) ==================
    // final h lives in parity (T_ & 1) == 0
    const float* hs = g_h[0][0];
    const float* hl = g_h[1][0];
    const int mt2 = bid >> 4;       // 0..7
    const int nt2 = bid & 15;       // 0..15
    const int b0e = mt2 * 64;
    const int n0e = nt2 * 32;
    unsigned* As2 = (unsigned*)smem_raw;    // [64][36]
    unsigned* Bs2 = As2 + 64 * 36;          // [32][36]

    const int wm2 = warp & 3;       // rows: 4 x 16
    const int wn2 = warp >> 2;      // cols: 2 x 16
    float acc2[2][4];
    #pragma unroll
    for (int n = 0; n < 2; ++n)
        #pragma unroll
        for (int r = 0; r < 4; ++r) acc2[n][r] = 0.0f;

    for (int kt = 0; kt < 32; ++kt) {
        const int k0 = kt * 32;
        __syncthreads();
        #pragma unroll
        for (int i = 0; i < 2; ++i) {
            int e  = tid + i * 256;   // 512 float4 total
            int m  = e >> 3;
            int kk = (e & 7) << 2;
            int k  = k0 + kk;
            float4 v = (k < H_)
                ? __ldcg((const float4*)(hs + (size_t)(b0e + m) * H_ + k))
                : __ldcg((const float4*)(hl + (size_t)(b0e + m) * H_ + (k - H_)));
            unsigned* d = As2 + m * 36 + kk;
            d[0] = f2tf32(v.x); d[1] = f2tf32(v.y);
            d[2] = f2tf32(v.z); d[3] = f2tf32(v.w);
        }
        {
            int e  = tid;             // 256 float4 total
            int kk = e >> 3;
            int c  = (e & 7) << 2;
            float4 v = __ldg((const float4*)(oW + (size_t)(k0 + kk) * H_ + n0e + c));
            unsigned* d = Bs2 + kk * 36 + c;
            d[0] = f2tf32(v.x); d[1] = f2tf32(v.y);
            d[2] = f2tf32(v.z); d[3] = f2tf32(v.w);
        }
        __syncthreads();
        #pragma unroll
        for (int kc = 0; kc < 32; kc += 8) {
            unsigned af[4];
            int rb = wm2 * 16;
            const unsigned* p = As2 + (rb + (lane >> 2)) * 36 + kc + (lane & 3);
            af[0] = p[0]; af[1] = p[8 * 36]; af[2] = p[4]; af[3] = p[8 * 36 + 4];
            #pragma unroll
            for (int nf = 0; nf < 2; ++nf) {
                int cb = wn2 * 16 + nf * 8;
                const unsigned* q = Bs2 + (kc + (lane & 3)) * 36 + cb + (lane >> 2);
                unsigned bf2[2] = { q[0], q[4 * 36] };
                mma8(acc2[nf], af, bf2);
            }
        }
    }

    #pragma unroll
    for (int nf = 0; nf < 2; ++nf) {
        int row = b0e + wm2 * 16 + (lane >> 2);
        int col = n0e + wn2 * 16 + nf * 8 + ((lane & 3) << 1);
        out[(size_t)row * H_ + col]           = tanhf(acc2[nf][0] + ob[col]);
        out[(size_t)row * H_ + col + 1]       = tanhf(acc2[nf][1] + ob[col + 1]);
        out[(size_t)(row + 8) * H_ + col]     = tanhf(acc2[nf][2] + ob[col]);
        out[(size_t)(row + 8) * H_ + col + 1] = tanhf(acc2[nf][3] + ob[col + 1]);
    }
}

extern "C" void kernel_launch(void* const* d_in, const int* in_sizes, int n_in,
                              void* d_out, int out_size) {
    (void)in_sizes; (void)n_in; (void)out_size;
    const float* s_x = (const float*)d_in[0];
    const float* l_x = (const float*)d_in[1];
    // d_in[2]=dow, d_in[3]=hour : unused by the reference
    const float* s_W = (const float*)d_in[4];
    const float* s_b = (const float*)d_in[5];
    const float* l_W = (const float*)d_in[6];
    const float* l_b = (const float*)d_in[7];
    const float* oW  = (const float*)d_in[8];
    const float* ob  = (const float*)d_in[9];
    float* out = (float*)d_out;

    cudaFuncSetAttribute(dual_lstm_kernel,
                         cudaFuncAttributeMaxDynamicSharedMemorySize, SMEM_BYTES);
    dual_lstm_kernel<<<NBLK, NTHREADS, SMEM_BYTES>>>(s_x, l_x, s_W, s_b,
                                                     l_W, l_b, oW, ob, out);
}